// round 7
// baseline (speedup 1.0000x reference)
#include <cuda_runtime.h>

#define NQ 12
#define DIM 4096
#define ST 512     // setup threads
#define CT 256     // contract threads

typedef unsigned long long ull;

// Row vectors v_j[n] = <j|U|n>, packed lanes (j=0, j=1): (re, im) per n.
__device__ ulonglong2 g_v2[DIM];
// Split-K partials: [quarter][group][lane] -> (re, im) packed.
__device__ ulonglong2 g_part4[4][256][32];
// Per-group arrival counters (zero-init; reset by last CTA each run).
__device__ unsigned g_cnt[256];

// ---- packed f32x2 helpers ----
__device__ __forceinline__ ull pack2(float lo, float hi) {
    ull r; asm("mov.b64 %0, {%1, %2};" : "=l"(r) : "f"(lo), "f"(hi)); return r;
}
__device__ __forceinline__ ull bcast2(float v) { return pack2(v, v); }
__device__ __forceinline__ void unpack2(ull v, float& lo, float& hi) {
    asm("mov.b64 {%0, %1}, %2;" : "=f"(lo), "=f"(hi) : "l"(v));
}
__device__ __forceinline__ ull fma2(ull a, ull b, ull c) {
    ull d; asm("fma.rn.f32x2 %0, %1, %2, %3;" : "=l"(d) : "l"(a), "l"(b), "l"(c)); return d;
}
__device__ __forceinline__ ull mul2(ull a, ull b) {
    ull d; asm("mul.rn.f32x2 %0, %1, %2;" : "=l"(d) : "l"(a), "l"(b)); return d;
}
__device__ __forceinline__ ull add2(ull a, ull b) {
    ull d; asm("add.rn.f32x2 %0, %1, %2;" : "=l"(d) : "l"(a), "l"(b)); return d;
}

// Shared-memory mapping with 65-row pitch: bank-conflict-free for all passes.
__device__ __forceinline__ int pnm(int n) { return 65 * (n >> 6) + (n & 63); }

// 12-bit inverse Gray code (prefix XOR).
__device__ __forceinline__ int grayinv(int i) {
    i ^= i >> 1; i ^= i >> 2; i ^= i >> 4; i ^= i >> 8;
    return i;
}

__device__ __forceinline__ float2 cmulc(float2 a, float2 b) {
    return make_float2(a.x * b.x - a.y * b.y, a.x * b.y + a.y * b.x);
}
__device__ __forceinline__ float2 selE(float2 e, int bit) {   // bit ? e : conj(e)
    return make_float2(e.x, bit ? e.y : -e.y);
}
__device__ __forceinline__ void crot(ull& r, ull& i, float2 f) {
    ull fx = bcast2(f.x), fy = bcast2(f.y), nfy = bcast2(-f.y);
    ull nr = fma2(fx, r, mul2(nfy, i));
    ull ni = fma2(fx, i, mul2(fy, r));
    r = nr; i = ni;
}

// Per-pass index assignment (T = tid 0..511, k = 0..7 owns the pass's 3 bits).
__device__ __forceinline__ int idx_p(int p, int T, int k) {
    int t6 = T & 63, th = T >> 6;
    if (p == 0) return (t6 << 6) | (th << 3) | k;     // k = bits 0-2
    if (p == 1) return (t6 << 6) | (k << 3) | th;     // k = bits 3-5
    if (p == 2) return (th << 9) | (k << 6) | t6;     // k = bits 6-8
    return (k << 9) | (th << 6) | t6;                 // k = bits 9-11
}

// Row x RY gates: 3 gates, gate m on k-bit m (wire = 11 - basebit - m).
// Row transform: a' = c a + s b ; b' = -s a + c b.
__device__ __forceinline__ void apply3(const float* C, const float* S,
                                       int basebit, ull* vr, ull* vi)
{
#pragma unroll
    for (int m = 0; m < 3; ++m) {
        int wire = 11 - basebit - m;
        float c = C[wire], s = S[wire];
        ull c2 = bcast2(c), s2 = bcast2(s), ns2 = bcast2(-s);
#pragma unroll
        for (int k = 0; k < 8; ++k) {
            if (k & (1 << m)) continue;
            int k1 = k | (1 << m);
            ull ar = vr[k], ai = vi[k], br = vr[k1], bi = vi[k1];
            vr[k]  = fma2(c2, ar, mul2(s2, br));
            vi[k]  = fma2(c2, ai, mul2(s2, bi));
            vr[k1] = fma2(c2, br, mul2(ns2, ar));
            vi[k1] = fma2(c2, bi, mul2(ns2, ai));
        }
    }
}

__device__ __forceinline__ void ldp(const ull* sre, const ull* sim, int p, int T,
                                    ull* vr, ull* vi) {
#pragma unroll
    for (int k = 0; k < 8; ++k) {
        int pn = pnm(idx_p(p, T, k));
        vr[k] = sre[pn]; vi[k] = sim[pn];
    }
}
__device__ __forceinline__ void ldp0_gray(const ull* sre, const ull* sim, int T,
                                          ull* vr, ull* vi) {
#pragma unroll
    for (int k = 0; k < 8; ++k) {
        int pn = pnm(grayinv(idx_p(0, T, k)));
        vr[k] = sre[pn]; vi[k] = sim[pn];
    }
}
__device__ __forceinline__ void stp(ull* sre, ull* sim, int p, int T,
                                    const ull* vr, const ull* vi) {
#pragma unroll
    for (int k = 0; k < 8; ++k) {
        int pn = pnm(idx_p(p, T, k));
        sre[pn] = vr[k]; sim[pn] = vi[k];
    }
}

// Diagonal (pass-0 layout). E[q] = e^{+i ang_q/2}; factor = prod selE(E, bit).
// idx bits [11..6]=T&63, [5..3]=T>>6, [2..0]=k; wire w <-> idx bit 11-w.
__device__ __forceinline__ void diag_p0(const float2* E, int T, ull* vr, ull* vi) {
    float2 tp = selE(E[0], (T >> 5) & 1);
#pragma unroll
    for (int w = 1; w < 6; ++w) tp = cmulc(tp, selE(E[w], (T >> (5 - w)) & 1));
#pragma unroll
    for (int w = 6; w < 9; ++w) tp = cmulc(tp, selE(E[w], (T >> (14 - w)) & 1));
#pragma unroll
    for (int k = 0; k < 8; ++k) {
        float2 kt = cmulc(selE(E[9], (k >> 2) & 1),
                          cmulc(selE(E[10], (k >> 1) & 1), selE(E[11], k & 1)));
        crot(vr[k], vi[k], cmulc(tp, kt));
    }
}

// Diagonal (pass-3 layout). idx bits [11..9]=k, [8..0]=T.
__device__ __forceinline__ void diag_p3(const float2* E, int T, ull* vr, ull* vi) {
    float2 tp = selE(E[3], (T >> 8) & 1);
#pragma unroll
    for (int w = 4; w < 12; ++w) tp = cmulc(tp, selE(E[w], (T >> (11 - w)) & 1));
#pragma unroll
    for (int k = 0; k < 8; ++k) {
        float2 kt = cmulc(selE(E[0], (k >> 2) & 1),
                          cmulc(selE(E[1], (k >> 1) & 1), selE(E[2], k & 1)));
        crot(vr[k], vi[k], cmulc(tp, kt));
    }
}

// ====================== SETUP: v = rows <j|U (512 threads, radix-8) =========
__global__ __launch_bounds__(ST)
void setup_kernel(const float* __restrict__ params)
{
    extern __shared__ ull smem[];
    ull* sre = smem;           // 64 rows x 65 pitch = 4160 ull
    ull* sim = smem + 4160;
    __shared__ float  sC[3][12], sS[3][12];
    __shared__ float2 sEA[3][12], sEB[3][12];   // e^{+i alpha/2}, e^{+i beta/2}

    const int T = threadIdx.x;

    if (T < 36) {
        int layer = T / 12, q = T % 12;
        const float* p = params + T * 3;
        float sa, ca; sincosf(0.5f * p[0], &sa, &ca);
        float sb, cb; sincosf(0.5f * p[1], &sb, &cb);
        float sc, cc; sincosf(0.5f * p[2], &sc, &cc);
        float2 m00 = make_float2( cb * ca, -sb * sa);
        float2 m10 = make_float2( cb * sa, -sb * ca);
        float2 e0 = make_float2(cc, -sc);
        float2 e1 = make_float2(cc,  sc);
        float2 u00 = cmulc(e0, m00);
        float2 u10 = cmulc(e1, m10);
        float ct = sqrtf(u00.x * u00.x + u00.y * u00.y);
        float st = sqrtf(u10.x * u10.x + u10.y * u10.y);
        float ApB = -2.0f * atan2f(u00.y, u00.x);
        float AmB =  2.0f * atan2f(u10.y, u10.x);
        float alpha = 0.5f * (ApB + AmB);
        float beta  = 0.5f * (ApB - AmB);
        sC[layer][q] = ct; sS[layer][q] = st;
        float s2, c2;
        sincosf(0.5f * alpha, &s2, &c2); sEA[layer][q] = make_float2(c2, s2);
        sincosf(0.5f * beta,  &s2, &c2); sEB[layer][q] = make_float2(c2, s2);
    }
    __syncthreads();

    ull vr[8], vi[8];

    // ---- Analytic layer-2 row at m = grayinv(idx), pass-0 ownership.
    // r2[m] = prod_q ryrow_q(m_q) * dbeta2[m]  (alpha2 = per-j global phase).
    {
        int t6 = T & 63, th = T >> 6;
        int thi = (t6 << 3) | th;               // idx bits 11..3
        int pt = __popc(thi) & 1;
        int mh = thi ^ (thi >> 1); mh ^= mh >> 2; mh ^= mh >> 4; mh ^= mh >> 8;
        float realH = 1.0f;
        float2 cH = make_float2(1.0f, 0.0f);
#pragma unroll
        for (int w = 0; w < 9; ++w) {           // wires 0..8 <- mh bits 8..0
            int bit = (mh >> (8 - w)) & 1;
            realH *= bit ? -sS[2][w] : sC[2][w];
            cH = cmulc(cH, selE(sEB[2][w], bit));
        }
        // Tables over mlo: bit2->wire9, bit1->wire10, bit0->wire11 (lane split)
        float realT[8]; ull rA[8]; float2 cT[8];
#pragma unroll
        for (int m = 0; m < 8; ++m) {
            int b2 = (m >> 2) & 1, b1 = (m >> 1) & 1, b0 = m & 1;
            realT[m] = (b2 ? -sS[2][9] : sC[2][9]) * (b1 ? -sS[2][10] : sC[2][10]);
            rA[m] = pack2(b0 ? -sS[2][11] : sC[2][11],
                          b0 ?  sC[2][11] : sS[2][11]);
            cT[m] = cmulc(selE(sEB[2][9], b2),
                          cmulc(selE(sEB[2][10], b1), selE(sEB[2][11], b0)));
        }
#pragma unroll
        for (int k = 0; k < 8; ++k) {
            int g = (k ^ (k >> 1) ^ (k >> 2)) & 7;     // const per unrolled k
            float rt = pt ? realT[g ^ 7] : realT[g];
            ull   ra = pt ? rA[g ^ 7]    : rA[g];
            float2 ct2 = pt ? cT[g ^ 7]  : cT[g];
            ull rp = mul2(bcast2(realH * rt), ra);
            float2 d = cmulc(cH, ct2);
            vr[k] = mul2(rp, bcast2(d.x));
            vi[k] = mul2(rp, bcast2(d.y));
        }
    }

    // ---- layer 1: D_alpha1 -> 12 gates (4 passes) -> D_beta1
    diag_p0(sEA[1], T, vr, vi);
    apply3(sC[1], sS[1], 0, vr, vi);
    stp(sre, sim, 0, T, vr, vi);
    __syncthreads();
    ldp(sre, sim, 1, T, vr, vi);
    apply3(sC[1], sS[1], 3, vr, vi);
    stp(sre, sim, 1, T, vr, vi);
    __syncthreads();
    ldp(sre, sim, 2, T, vr, vi);
    apply3(sC[1], sS[1], 6, vr, vi);
    stp(sre, sim, 2, T, vr, vi);
    __syncthreads();
    ldp(sre, sim, 3, T, vr, vi);
    apply3(sC[1], sS[1], 9, vr, vi);
    diag_p3(sEB[1], T, vr, vi);
    stp(sre, sim, 3, T, vr, vi);
    __syncthreads();

    // ---- layer 0: P gather -> D_alpha0 -> 12 gates -> D_beta0 -> g_v2
    ldp0_gray(sre, sim, T, vr, vi);
    diag_p0(sEA[0], T, vr, vi);
    apply3(sC[0], sS[0], 0, vr, vi);
    stp(sre, sim, 0, T, vr, vi);
    __syncthreads();
    ldp(sre, sim, 1, T, vr, vi);
    apply3(sC[0], sS[0], 3, vr, vi);
    stp(sre, sim, 1, T, vr, vi);
    __syncthreads();
    ldp(sre, sim, 2, T, vr, vi);
    apply3(sC[0], sS[0], 6, vr, vi);
    stp(sre, sim, 2, T, vr, vi);
    __syncthreads();
    ldp(sre, sim, 3, T, vr, vi);
    apply3(sC[0], sS[0], 9, vr, vi);
    diag_p3(sEB[0], T, vr, vi);
#pragma unroll
    for (int k = 0; k < 8; ++k) {
        int n = idx_p(3, T, k);
        g_v2[n] = make_ulonglong2(vr[k], vi[k]);
    }
}

// ====================== CONTRACT (quarter split-K + fused combine) ==========
// blockIdx: quarter = bx & 3 (hi rows [q*16, q*16+16)), group = bx >> 2.
// Warp w owns 2 rows; lanes = 32 batch elements.
__global__ __launch_bounds__(CT, 3)
void contract_kernel(const float* __restrict__ x, float* __restrict__ out, int B)
{
    __shared__ ulonglong2 sv[1024];          // quarter v slice: [row16][lo64]
    __shared__ ull pre[8][32], pim[8][32];
    __shared__ unsigned s_last;

    const int tid = threadIdx.x;
    const int lane = tid & 31;
    const int warpid = tid >> 5;
    const int quarter = blockIdx.x & 3;
    const int group = blockIdx.x >> 2;

#pragma unroll
    for (int i = 0; i < 4; ++i)
        sv[tid + i * CT] = g_v2[quarter * 1024 + tid + i * CT];

    int b = group * 32 + lane;
    int bb = (b < B) ? b : (B - 1);

    ull  b2p[8];
    float a2f[8], hfac[2];
    {
        float fc[NQ], fs[NQ];
#pragma unroll
        for (int w = 0; w < NQ; ++w) {
            float s, c; __sincosf(0.5f * x[bb * NQ + w], &s, &c);
            fc[w] = c; fs[w] = s;
        }
#pragma unroll
        for (int i = 0; i < 8; ++i) {
            a2f[i] = ((i & 1) ? fs[8] : fc[8]) *
                     ((i & 2) ? fs[7] : fc[7]) *
                     ((i & 4) ? fs[6] : fc[6]);
            float bv = ((i & 1) ? fs[11] : fc[11]) *
                       ((i & 2) ? fs[10] : fc[10]) *
                       ((i & 4) ? fs[9]  : fc[9]);
            b2p[i] = bcast2(bv);
        }
#pragma unroll
        for (int t = 0; t < 2; ++t) {
            int row = quarter * 16 + warpid * 2 + t;   // hi bits 5..0 -> wires 0..5
            hfac[t] = (((row >> 5) & 1) ? fs[0] : fc[0]) *
                      (((row >> 4) & 1) ? fs[1] : fc[1]) *
                      (((row >> 3) & 1) ? fs[2] : fc[2]) *
                      (((row >> 2) & 1) ? fs[3] : fc[3]) *
                      (((row >> 1) & 1) ? fs[4] : fc[4]) *
                      (((row >> 0) & 1) ? fs[5] : fc[5]);
        }
    }
    __syncthreads();

    const ulonglong2* vw = sv + warpid * 128;
    ull ir[2] = {0ULL, 0ULL}, ii[2] = {0ULL, 0ULL};

#pragma unroll
    for (int i = 0; i < 8; ++i) {
        ull tr[2] = {0ULL, 0ULL}, ti[2] = {0ULL, 0ULL};
#pragma unroll
        for (int j = 0; j < 8; ++j) {
#pragma unroll
            for (int t = 0; t < 2; ++t) {
                ulonglong2 v = vw[t * 64 + i * 8 + j];   // warp-broadcast LDS
                tr[t] = fma2(v.x, b2p[j], tr[t]);
                ti[t] = fma2(v.y, b2p[j], ti[t]);
            }
        }
        ull ai = bcast2(a2f[i]);
#pragma unroll
        for (int t = 0; t < 2; ++t) {
            ir[t] = fma2(ai, tr[t], ir[t]);
            ii[t] = fma2(ai, ti[t], ii[t]);
        }
    }

    ull amp_re = 0ULL, amp_im = 0ULL;
#pragma unroll
    for (int t = 0; t < 2; ++t) {
        ull hc = bcast2(hfac[t]);
        amp_re = fma2(hc, ir[t], amp_re);
        amp_im = fma2(hc, ii[t], amp_im);
    }
    pre[warpid][lane] = amp_re;
    pim[warpid][lane] = amp_im;
    __syncthreads();

    if (warpid == 0) {
        ull re = pre[0][lane], im = pim[0][lane];
#pragma unroll
        for (int w = 1; w < 8; ++w) {
            re = add2(re, pre[w][lane]);
            im = add2(im, pim[w][lane]);
        }
        g_part4[quarter][group][lane] = make_ulonglong2(re, im);
    }
    __syncthreads();

    // Arrival count; last CTA of the group combines (fixed order -> deterministic).
    if (tid == 0) {
        __threadfence();
        unsigned old = atomicAdd(&g_cnt[group], 1u);
        s_last = (old == 3u) ? 1u : 0u;
    }
    __syncthreads();

    if (s_last && warpid == 0) {
        __threadfence();
        ull re = 0ULL, im = 0ULL;
#pragma unroll
        for (int q = 0; q < 4; ++q) {
            ulonglong2 p = __ldcg(&g_part4[q][group][lane]);
            re = add2(re, p.x);
            im = add2(im, p.y);
        }
        float r0, r1, i0, i1;
        unpack2(re, r0, r1);
        unpack2(im, i0, i1);
        float q0 = r0 * r0 + i0 * i0;
        float q1 = r1 * r1 + i1 * i1;
        float inv = 1.0f / (q0 + q1);
        if (b < B) ((float2*)out)[b] = make_float2(q0 * inv, q1 * inv);
        if (lane == 0) g_cnt[group] = 0;     // reset for next graph replay
    }
}

extern "C" void kernel_launch(void* const* d_in, const int* in_sizes, int n_in,
                              void* d_out, int out_size) {
    const float* x      = (const float*)d_in[0];  // (B, 12) float32
    const float* params = (const float*)d_in[1];  // (3, 12, 3) float32
    float* out = (float*)d_out;                   // (B, 2) float32
    int B = in_sizes[0] / NQ;
    int groups = (B + 31) / 32;

    size_t sh_setup = 2ull * 4160 * sizeof(ull);   // 66560 B
    static bool attr_done = false;
    if (!attr_done) {
        cudaFuncSetAttribute(setup_kernel,
                             cudaFuncAttributeMaxDynamicSharedMemorySize,
                             (int)sh_setup);
        attr_done = true;
    }

    setup_kernel<<<1, ST, sh_setup>>>(params);
    contract_kernel<<<groups * 4, CT>>>(x, out, B);
}